// round 10
// baseline (speedup 1.0000x reference)
#include <cuda_runtime.h>
#include <cuda_bf16.h>
#include <cstddef>

// Problem constants: N=50000, DEG=32, E=N*32, F=64, K=3, DIM=2, L=3
#define MAXN 50000
#define MAXE (MAXN * 32)
#define FDIM 64
#define KF   192        // K * F
#define TILE 32

// smem: gs[32][192] row-major + wf4[8][32] float4 staging = 28672 B -> 6 CTAs/SM
#define GS_FLOATS (TILE * KF)
#define SMEM_FLOATS (GS_FLOATS + 8 * 32 * 4)
#define SMEM_BYTES  (SMEM_FLOATS * 4)

__device__ float h_bufA[(size_t)MAXN * FDIM];
__device__ float h_bufB[(size_t)MAXN * FDIM];
// WP[layer][pp][t] float4 = {Wk[2pp][2t], Wk[2pp+1][2t], Wk[2pp][2t+1], Wk[2pp+1][2t+1]}
__device__ float WP_buf[3 * 96 * 32 * 4];
// wpack[layer][e] = {w0, w1, w2, bitcast(src)}
__device__ float4 wpack_buf[(size_t)3 * MAXE];

// Packed fp32x2 FMA (sm_103a FFMA2 — only reachable via PTX)
#define FMA_F32X2(d, a, b, c) \
    asm("fma.rn.f32x2 %0, %1, %2, %3;" : "=l"(d) : "l"(a), "l"(b), "l"(c))
#define PACK_DUP(d, x) \
    asm("mov.b64 %0, {%1, %1};" : "=l"(d) : "f"(x))
#define UNPACK2(lo, hi, v) \
    asm("mov.b64 {%0, %1}, %2;" : "=f"(lo), "=f"(hi) : "l"(v))

typedef unsigned long long ull;

// ---------------------------------------------------------------------------
// Prep 1: per-edge Gaussian weights for every layer.
// ---------------------------------------------------------------------------
__global__ void prep_w(const float* __restrict__ pseudo,
                       const int*   __restrict__ colind,
                       const float* __restrict__ projW,   // [L,2,2]
                       const float* __restrict__ projb,   // [L,2]
                       const float* __restrict__ mu,      // [L,3,2]
                       const float* __restrict__ isg,     // [L,3,2]
                       int nE, int nL)
{
    const int idx = blockIdx.x * 256 + threadIdx.x;
    if (idx >= nE * nL) return;
    const int i = idx / nE;      // layer
    const int e = idx - i * nE;

    const float W00 = __ldg(&projW[i*4+0]), W01 = __ldg(&projW[i*4+1]);
    const float W10 = __ldg(&projW[i*4+2]), W11 = __ldg(&projW[i*4+3]);
    const float b0 = __ldg(&projb[i*2+0]), b1 = __ldg(&projb[i*2+1]);

    const float2 ps = __ldg(&((const float2*)pseudo)[e]);
    const float u0 = tanhf(fmaf(ps.y, W10, fmaf(ps.x, W00, b0)));
    const float u1 = tanhf(fmaf(ps.y, W11, fmaf(ps.x, W01, b1)));

    float4 v;
    {
        float q0 = __ldg(&isg[i*6+0]), q1 = __ldg(&isg[i*6+1]);
        float d0 = u0 - __ldg(&mu[i*6+0]), d1 = u1 - __ldg(&mu[i*6+1]);
        v.x = __expf(-0.5f * (d0*d0*q0*q0 + d1*d1*q1*q1));
        q0 = __ldg(&isg[i*6+2]); q1 = __ldg(&isg[i*6+3]);
        d0 = u0 - __ldg(&mu[i*6+2]); d1 = u1 - __ldg(&mu[i*6+3]);
        v.y = __expf(-0.5f * (d0*d0*q0*q0 + d1*d1*q1*q1));
        q0 = __ldg(&isg[i*6+4]); q1 = __ldg(&isg[i*6+5]);
        d0 = u0 - __ldg(&mu[i*6+4]); d1 = u1 - __ldg(&mu[i*6+5]);
        v.z = __expf(-0.5f * (d0*d0*q0*q0 + d1*d1*q1*q1));
    }
    v.w = __int_as_float(__ldg(&colind[e]));
    wpack_buf[(size_t)i * nE + e] = v;
}

// ---------------------------------------------------------------------------
// Prep 2: rearrange fcW into WP layout (K-pair-packed, warp-coalesced).
// ---------------------------------------------------------------------------
__global__ void prep_kernel(const float* __restrict__ fcW, int nL)
{
    const int idx = blockIdx.x * 256 + threadIdx.x;
    const int total = nL * 96 * 32;
    if (idx >= total) return;
    const int i  = idx / (96 * 32);
    const int rem = idx - i * 96 * 32;
    const int pp = rem >> 5, t = rem & 31;
    const float* W = fcW + i * 64 * 192;
    const int p0 = 2 * pp, p1 = 2 * pp + 1;
    const int k0 = p0 >> 6, j0 = p0 & 63;
    const int k1 = p1 >> 6, j1 = p1 & 63;
    float4 v;
    v.x = W[j0 * 192 + k0 * 64 + 2 * t];
    v.y = W[j1 * 192 + k1 * 64 + 2 * t];
    v.z = W[j0 * 192 + k0 * 64 + 2 * t + 1];
    v.w = W[j1 * 192 + k1 * 64 + 2 * t + 1];
    ((float4*)WP_buf)[idx] = v;
}

// ---------------------------------------------------------------------------
// Fused layer kernel: tiny footprint for 6 CTAs/SM (48 warps).
//   phase A: 8 warps x 4 nodes -> gs[r][p]; staging = 1 LDG.128/lane
//   phase B: block GEMM, g broadcast LDS.128 + W coalesced LDG (L1)
// ---------------------------------------------------------------------------
__global__ __launch_bounds__(256, 6)
void fused_layer(const float* __restrict__ h,
                 const int*   __restrict__ rowptr,
                 const float4* __restrict__ wpack,   // [E] this layer
                 const float* __restrict__ WP,       // [96][32] float4
                 float* __restrict__ out, int n)
{
    extern __shared__ float smem[];
    float* gs = smem;                               // [32][192]
    float4* wf4 = (float4*)(smem + GS_FLOATS);      // [8][32]

    const int tid = threadIdx.x;
    const int wid = tid >> 5;
    const int lid = tid & 31;

    const ulonglong2* __restrict__ wpv = (const ulonglong2*)WP;

    // phase-B mapping
    const int tx = tid & 31;   // cols 2tx, 2tx+1
    const int ty = tid >> 5;   // rows 4ty .. +3

    const int ntiles = (n + TILE - 1) / TILE;
    for (int tile = blockIdx.x; tile < ntiles; tile += gridDim.x) {
        const int r0 = tile * TILE;
        const int rows = min(TILE, n - r0);
        __syncthreads();   // prev phase-B readers done

        // ---------------- Phase A: aggregation ---------------------------
        {
            float4* wfw = wf4 + (wid << 5);
            for (int j = 0; j < 4; j++) {
                const int r = (wid << 2) + j;
                const int node = r0 + r;
                if (node >= n) break;

                const int e0 = rowptr[node], e1 = rowptr[node + 1];
                ull A0 = 0ULL, A1 = 0ULL, A2 = 0ULL;

                for (int base = e0; base < e1; base += 32) {
                    const int cnt = min(32, e1 - base);
                    if (lid < cnt)
                        wfw[lid] = __ldg(&wpack[base + lid]);
                    __syncwarp();
                    if (cnt == 32) {
                        #pragma unroll 8
                        for (int t = 0; t < 32; t++) {
                            const float4 wt = wfw[t];
                            const int src = __float_as_int(wt.w);
                            const ull hv = *(const ull*)(h + (size_t)src * FDIM + 2 * lid);
                            ull w0d, w1d, w2d;
                            PACK_DUP(w0d, wt.x); PACK_DUP(w1d, wt.y); PACK_DUP(w2d, wt.z);
                            FMA_F32X2(A0, hv, w0d, A0);
                            FMA_F32X2(A1, hv, w1d, A1);
                            FMA_F32X2(A2, hv, w2d, A2);
                        }
                    } else {
                        for (int t = 0; t < cnt; t++) {
                            const float4 wt = wfw[t];
                            const int src = __float_as_int(wt.w);
                            const ull hv = *(const ull*)(h + (size_t)src * FDIM + 2 * lid);
                            ull w0d, w1d, w2d;
                            PACK_DUP(w0d, wt.x); PACK_DUP(w1d, wt.y); PACK_DUP(w2d, wt.z);
                            FMA_F32X2(A0, hv, w0d, A0);
                            FMA_F32X2(A1, hv, w1d, A1);
                            FMA_F32X2(A2, hv, w2d, A2);
                        }
                    }
                    __syncwarp();
                }
                *(ull*)(gs + r * KF + 2 * lid      ) = A0;
                *(ull*)(gs + r * KF + 2 * lid +  64) = A1;
                *(ull*)(gs + r * KF + 2 * lid + 128) = A2;
            }
        }
        __syncthreads();

        // ---------------- Phase B: GEMM ----------------------------------
        {
            const ull* gp = (const ull*)(gs + (ty << 2) * KF);

            ull acc[4][2];
            #pragma unroll
            for (int i = 0; i < 4; i++) { acc[i][0] = 0ULL; acc[i][1] = 0ULL; }

            #pragma unroll 4
            for (int pp2 = 0; pp2 < 48; pp2++) {
                const ulonglong2 wA = __ldg(&wpv[(2 * pp2    ) * 32 + tx]);
                const ulonglong2 wB = __ldg(&wpv[(2 * pp2 + 1) * 32 + tx]);
                #pragma unroll
                for (int i = 0; i < 4; i++) {
                    const ulonglong2 gv = *(const ulonglong2*)(gp + i * 96 + 2 * pp2);
                    FMA_F32X2(acc[i][0], gv.x, wA.x, acc[i][0]);
                    FMA_F32X2(acc[i][1], gv.x, wA.y, acc[i][1]);
                    FMA_F32X2(acc[i][0], gv.y, wB.x, acc[i][0]);
                    FMA_F32X2(acc[i][1], gv.y, wB.y, acc[i][1]);
                }
            }

            #pragma unroll
            for (int i = 0; i < 4; i++) {
                const int r = (ty << 2) + i;
                if (r < rows) {
                    float e0, o0, e1, o1;
                    UNPACK2(e0, o0, acc[i][0]);
                    UNPACK2(e1, o1, acc[i][1]);
                    *(float2*)&out[(size_t)(r0 + r) * FDIM + 2 * tx] =
                        make_float2(e0 + o0, e1 + o1);
                }
            }
        }
    }
}

// ---------------------------------------------------------------------------
extern "C" void kernel_launch(void* const* d_in, const int* in_sizes, int n_in,
                              void* d_out, int out_size)
{
    const float* feat   = (const float*)d_in[0];
    const float* pseudo = (const float*)d_in[1];
    const int*   rowptr = (const int*)  d_in[2];
    const int*   colind = (const int*)  d_in[3];
    const float* projW  = (const float*)d_in[4];  // [L,2,2]
    const float* projb  = (const float*)d_in[5];  // [L,2]
    const float* fcW    = (const float*)d_in[6];  // [L,64,192]
    const float* mu     = (const float*)d_in[7];  // [L,3,2]
    const float* isg    = (const float*)d_in[8];  // [L,3,2]

    const int n  = in_sizes[0] / FDIM;
    const int nE = in_sizes[3];
    const int nL = in_sizes[6] / (FDIM * KF);

    void *hap, *hbp, *wpp, *wkp;
    cudaGetSymbolAddress(&hap, h_bufA);
    cudaGetSymbolAddress(&hbp, h_bufB);
    cudaGetSymbolAddress(&wpp, WP_buf);
    cudaGetSymbolAddress(&wkp, wpack_buf);
    float* hbufs[2] = { (float*)hap, (float*)hbp };
    const float* WP = (const float*)wpp;
    const float4* wpack = (const float4*)wkp;

    cudaFuncSetAttribute(fused_layer, cudaFuncAttributeMaxDynamicSharedMemorySize, SMEM_BYTES);

    prep_kernel<<<(nL * 96 * 32 + 255) / 256, 256>>>(fcW, nL);
    prep_w<<<((size_t)nE * nL + 255) / 256, 256>>>(pseudo, colind, projW, projb,
                                                   mu, isg, nE, nL);

    const int ntiles = (n + TILE - 1) / TILE;
    const int maxg = 6 * 148;
    const int grid = ntiles < maxg ? ntiles : maxg;

    const float* hin = feat;
    for (int i = 0; i < nL; i++) {
        float* hout = (i == nL - 1) ? (float*)d_out : hbufs[i & 1];
        fused_layer<<<grid, 256, SMEM_BYTES>>>(hin, rowptr,
                                               wpack + (size_t)i * nE,
                                               WP + (size_t)i * 96 * 32 * 4,
                                               hout, n);
        hin = hout;
    }
}

// round 12
// speedup vs baseline: 1.0380x; 1.0380x over previous
#include <cuda_runtime.h>
#include <cuda_bf16.h>
#include <cstddef>
#include <cstdint>

// Problem constants: N=50000, DEG=32, E=N*32, F=64, K=3, DIM=2, L=3
#define MAXN 50000
#define MAXE (MAXN * 32)
#define FDIM 64
#define KF   192        // K * F
#define RPW  8          // rows (nodes) per warp tile

// smem: WPs[96][32] ulonglong2 (49152 B) + gs[8 warps][8 rows][192] (49152 B)
#define WPS_FLOATS (96 * 32 * 4)
#define GS_FLOATS  (8 * RPW * KF)
#define SMEM_FLOATS (WPS_FLOATS + GS_FLOATS)
#define SMEM_BYTES  (SMEM_FLOATS * 4)     // 98304 -> 2 CTAs/SM

__device__ float h_bufA[(size_t)MAXN * FDIM];
__device__ float h_bufB[(size_t)MAXN * FDIM];
// WP[layer][pp][t] float4 = {Wk[2pp][2t], Wk[2pp+1][2t], Wk[2pp][2t+1], Wk[2pp+1][2t+1]}
__device__ float WP_buf[3 * 96 * 32 * 4];
// wpack[layer][e] = {w0, w1, w2, bitcast(src)}
__device__ float4 wpack_buf[(size_t)3 * MAXE];

// Packed fp32x2 FMA (sm_103a FFMA2 — only reachable via PTX)
#define FMA_F32X2(d, a, b, c) \
    asm("fma.rn.f32x2 %0, %1, %2, %3;" : "=l"(d) : "l"(a), "l"(b), "l"(c))
#define PACK_DUP(d, x) \
    asm("mov.b64 %0, {%1, %1};" : "=l"(d) : "f"(x))
#define UNPACK2(lo, hi, v) \
    asm("mov.b64 {%0, %1}, %2;" : "=f"(lo), "=f"(hi) : "l"(v))

typedef unsigned long long ull;

// ---------------------------------------------------------------------------
// Prep 1: per-edge Gaussian weights for every layer (removes MUFU chain from
// the hot kernel; proven round 10).
// ---------------------------------------------------------------------------
__global__ void prep_w(const float* __restrict__ pseudo,
                       const int*   __restrict__ colind,
                       const float* __restrict__ projW,
                       const float* __restrict__ projb,
                       const float* __restrict__ mu,
                       const float* __restrict__ isg,
                       int nE, int nL)
{
    const int idx = blockIdx.x * 256 + threadIdx.x;
    if (idx >= nE * nL) return;
    const int i = idx / nE;
    const int e = idx - i * nE;

    const float W00 = __ldg(&projW[i*4+0]), W01 = __ldg(&projW[i*4+1]);
    const float W10 = __ldg(&projW[i*4+2]), W11 = __ldg(&projW[i*4+3]);
    const float b0 = __ldg(&projb[i*2+0]), b1 = __ldg(&projb[i*2+1]);

    const float2 ps = __ldg(&((const float2*)pseudo)[e]);
    const float u0 = tanhf(fmaf(ps.y, W10, fmaf(ps.x, W00, b0)));
    const float u1 = tanhf(fmaf(ps.y, W11, fmaf(ps.x, W01, b1)));

    float4 v;
    {
        float q0 = __ldg(&isg[i*6+0]), q1 = __ldg(&isg[i*6+1]);
        float d0 = u0 - __ldg(&mu[i*6+0]), d1 = u1 - __ldg(&mu[i*6+1]);
        v.x = __expf(-0.5f * (d0*d0*q0*q0 + d1*d1*q1*q1));
        q0 = __ldg(&isg[i*6+2]); q1 = __ldg(&isg[i*6+3]);
        d0 = u0 - __ldg(&mu[i*6+2]); d1 = u1 - __ldg(&mu[i*6+3]);
        v.y = __expf(-0.5f * (d0*d0*q0*q0 + d1*d1*q1*q1));
        q0 = __ldg(&isg[i*6+4]); q1 = __ldg(&isg[i*6+5]);
        d0 = u0 - __ldg(&mu[i*6+4]); d1 = u1 - __ldg(&mu[i*6+5]);
        v.z = __expf(-0.5f * (d0*d0*q0*q0 + d1*d1*q1*q1));
    }
    v.w = __int_as_float(__ldg(&colind[e]));
    wpack_buf[(size_t)i * nE + e] = v;
}

// ---------------------------------------------------------------------------
// Prep 2: rearrange fcW into WP layout (K-pair-packed; proven round 8).
// ---------------------------------------------------------------------------
__global__ void prep_kernel(const float* __restrict__ fcW, int nL)
{
    const int idx = blockIdx.x * 256 + threadIdx.x;
    const int total = nL * 96 * 32;
    if (idx >= total) return;
    const int i  = idx / (96 * 32);
    const int rem = idx - i * 96 * 32;
    const int pp = rem >> 5, t = rem & 31;
    const float* W = fcW + i * 64 * 192;
    const int p0 = 2 * pp, p1 = 2 * pp + 1;
    const int k0 = p0 >> 6, j0 = p0 & 63;
    const int k1 = p1 >> 6, j1 = p1 & 63;
    float4 v;
    v.x = W[j0 * 192 + k0 * 64 + 2 * t];
    v.y = W[j1 * 192 + k1 * 64 + 2 * t];
    v.z = W[j0 * 192 + k0 * 64 + 2 * t + 1];
    v.w = W[j1 * 192 + k1 * 64 + 2 * t + 1];
    ((float4*)WP_buf)[idx] = v;
}

// ---------------------------------------------------------------------------
// Free-running fused layer kernel: each warp owns an 8-node tile end-to-end.
// NO __syncthreads after init — warps desync so gather (L2-bound) and GEMM
// (FFMA2-bound) phases from different warps overlap on the SM continuously.
// Staging buffer = the smem row currently being gathered (zero extra smem).
// ---------------------------------------------------------------------------
__global__ __launch_bounds__(256, 2)
void fused_layer(const float* __restrict__ h,
                 const int*   __restrict__ rowptr,
                 const float4* __restrict__ wpack,   // [E] this layer
                 const float* __restrict__ WP,       // [96][32] float4
                 float* __restrict__ out, int n)
{
    extern __shared__ float smem[];
    float* WPs = smem;                    // [96][32] ulonglong2 view
    float* gs  = smem + WPS_FLOATS;       // [8 warps][RPW][192]

    const int tid = threadIdx.x;
    const int wid = tid >> 5;
    const int lid = tid & 31;

    // Load W into smem once (coalesced), single barrier of the kernel.
    for (int i = tid; i < 96 * 32; i += 256)
        ((float4*)WPs)[i] = __ldg((const float4*)WP + i);
    __syncthreads();

    float* grow = gs + wid * (RPW * KF);          // this warp's 8 rows
    const ulonglong2* wps2 = (const ulonglong2*)WPs;

    const int ntiles = (n + RPW - 1) / RPW;
    const int gwarp  = blockIdx.x * 8 + wid;
    const int nwarps = gridDim.x * 8;

    for (int tile = gwarp; tile < ntiles; tile += nwarps) {
        const int r0 = tile * RPW;

        // ---------------- gather 8 nodes into grow ----------------------
        for (int j = 0; j < RPW; j++) {
            const int node = r0 + j;
            if (node >= n) break;

            float4* stage = (float4*)(grow + j * KF);   // 768B row >= 512B stage
            const int e0 = rowptr[node], e1 = rowptr[node + 1];
            ull A0 = 0ULL, A1 = 0ULL, A2 = 0ULL;

            for (int base = e0; base < e1; base += 32) {
                const int cnt = min(32, e1 - base);
                if (lid < cnt)
                    stage[lid] = __ldg(&wpack[base + lid]);
                __syncwarp();
                if (cnt == 32) {
                    #pragma unroll 8
                    for (int t = 0; t < 32; t++) {
                        const float4 wt = stage[t];
                        const int src = __float_as_int(wt.w);
                        const ull hv = *(const ull*)(h + (size_t)src * FDIM + 2 * lid);
                        ull w0d, w1d, w2d;
                        PACK_DUP(w0d, wt.x); PACK_DUP(w1d, wt.y); PACK_DUP(w2d, wt.z);
                        FMA_F32X2(A0, hv, w0d, A0);
                        FMA_F32X2(A1, hv, w1d, A1);
                        FMA_F32X2(A2, hv, w2d, A2);
                    }
                } else {
                    for (int t = 0; t < cnt; t++) {
                        const float4 wt = stage[t];
                        const int src = __float_as_int(wt.w);
                        const ull hv = *(const ull*)(h + (size_t)src * FDIM + 2 * lid);
                        ull w0d, w1d, w2d;
                        PACK_DUP(w0d, wt.x); PACK_DUP(w1d, wt.y); PACK_DUP(w2d, wt.z);
                        FMA_F32X2(A0, hv, w0d, A0);
                        FMA_F32X2(A1, hv, w1d, A1);
                        FMA_F32X2(A2, hv, w2d, A2);
                    }
                }
                __syncwarp();
            }
            // overwrite row j (staging consumed)
            *(ull*)(grow + j * KF + 2 * lid      ) = A0;
            *(ull*)(grow + j * KF + 2 * lid +  64) = A1;
            *(ull*)(grow + j * KF + 2 * lid + 128) = A2;
            __syncwarp();
        }

        // ---------------- GEMM the warp's 8 rows -------------------------
        ull acc[RPW][2];
        #pragma unroll
        for (int i = 0; i < RPW; i++) { acc[i][0] = 0ULL; acc[i][1] = 0ULL; }

        #pragma unroll 2
        for (int pp2 = 0; pp2 < 48; pp2++) {
            const ulonglong2 wA = wps2[(2 * pp2    ) * 32 + lid];
            const ulonglong2 wB = wps2[(2 * pp2 + 1) * 32 + lid];
            #pragma unroll
            for (int i = 0; i < RPW; i++) {
                const ulonglong2 gv =
                    *(const ulonglong2*)(grow + i * KF + 4 * pp2);
                FMA_F32X2(acc[i][0], gv.x, wA.x, acc[i][0]);
                FMA_F32X2(acc[i][1], gv.x, wA.y, acc[i][1]);
                FMA_F32X2(acc[i][0], gv.y, wB.x, acc[i][0]);
                FMA_F32X2(acc[i][1], gv.y, wB.y, acc[i][1]);
            }
        }

        #pragma unroll
        for (int i = 0; i < RPW; i++) {
            const int r = r0 + i;
            if (r < n) {
                float e0, o0, e1, o1;
                UNPACK2(e0, o0, acc[i][0]);
                UNPACK2(e1, o1, acc[i][1]);
                *(float2*)&out[(size_t)r * FDIM + 2 * lid] =
                    make_float2(e0 + o0, e1 + o1);
            }
        }
    }
}

// ---------------------------------------------------------------------------
extern "C" void kernel_launch(void* const* d_in, const int* in_sizes, int n_in,
                              void* d_out, int out_size)
{
    const float* feat   = (const float*)d_in[0];
    const float* pseudo = (const float*)d_in[1];
    const int*   rowptr = (const int*)  d_in[2];
    const int*   colind = (const int*)  d_in[3];
    const float* projW  = (const float*)d_in[4];
    const float* projb  = (const float*)d_in[5];
    const float* fcW    = (const float*)d_in[6];
    const float* mu     = (const float*)d_in[7];
    const float* isg    = (const float*)d_in[8];

    const int n  = in_sizes[0] / FDIM;
    const int nE = in_sizes[3];
    const int nL = in_sizes[6] / (FDIM * KF);

    void *hap, *hbp, *wpp, *wkp;
    cudaGetSymbolAddress(&hap, h_bufA);
    cudaGetSymbolAddress(&hbp, h_bufB);
    cudaGetSymbolAddress(&wpp, WP_buf);
    cudaGetSymbolAddress(&wkp, wpack_buf);
    float* hbufs[2] = { (float*)hap, (float*)hbp };
    const float* WP = (const float*)wpp;
    const float4* wpack = (const float4*)wkp;

    cudaFuncSetAttribute(fused_layer, cudaFuncAttributeMaxDynamicSharedMemorySize, SMEM_BYTES);

    prep_kernel<<<(nL * 96 * 32 + 255) / 256, 256>>>(fcW, nL);
    prep_w<<<((size_t)nE * nL + 255) / 256, 256>>>(pseudo, colind, projW, projb,
                                                   mu, isg, nE, nL);

    const int ntiles = (n + RPW - 1) / RPW;
    const int maxg = 2 * 148;
    int grid = (ntiles + 7) / 8;
    if (grid > maxg) grid = maxg;

    const float* hin = feat;
    for (int i = 0; i < nL; i++) {
        float* hout = (i == nL - 1) ? (float*)d_out : hbufs[i & 1];
        fused_layer<<<grid, 256, SMEM_BYTES>>>(hin, rowptr,
                                               wpack + (size_t)i * nE,
                                               WP + (size_t)i * 96 * 32 * 4,
                                               hout, n);
        hin = hout;
    }
}

// round 13
// speedup vs baseline: 1.2799x; 1.2330x over previous
#include <cuda_runtime.h>
#include <cuda_bf16.h>
#include <cstddef>
#include <cstdint>

// Problem constants: N=50000, DEG=32, E=N*32, F=64, K=3, DIM=2, L=3
#define MAXN 50000
#define MAXE (MAXN * 32)
#define FDIM 64
#define KF   192        // K * F
#define TILE 64

// smem: gs[64][192] (49152 B) + stage[8 warps][66] float4 (8448 B) = 57600 B -> 3 CTAs/SM
#define GS_FLOATS (TILE * KF)
#define STG_F4    66           // A: 0..31, B: 33..64 (16B pad between)
#define SMEM_FLOATS (GS_FLOATS + 8 * STG_F4 * 4)
#define SMEM_BYTES  (SMEM_FLOATS * 4)

__device__ float h_bufA[(size_t)MAXN * FDIM];
__device__ float h_bufB[(size_t)MAXN * FDIM];
// WP[layer][pp][t] float4 = {Wk[2pp][2t], Wk[2pp+1][2t], Wk[2pp][2t+1], Wk[2pp+1][2t+1]}
__device__ float WP_buf[3 * 96 * 32 * 4];
// wpack[layer][e] = {w0, w1, w2, bitcast(src)}
__device__ float4 wpack_buf[(size_t)3 * MAXE];

// Packed fp32x2 FMA (sm_103a FFMA2 — only reachable via PTX)
#define FMA_F32X2(d, a, b, c) \
    asm("fma.rn.f32x2 %0, %1, %2, %3;" : "=l"(d) : "l"(a), "l"(b), "l"(c))
#define PACK_DUP(d, x) \
    asm("mov.b64 %0, {%1, %1};" : "=l"(d) : "f"(x))
#define UNPACK2(lo, hi, v) \
    asm("mov.b64 {%0, %1}, %2;" : "=f"(lo), "=f"(hi) : "l"(v))

typedef unsigned long long ull;

// ---------------------------------------------------------------------------
// Prep 1: per-edge Gaussian weights for every layer.
// ---------------------------------------------------------------------------
__global__ void prep_w(const float* __restrict__ pseudo,
                       const int*   __restrict__ colind,
                       const float* __restrict__ projW,
                       const float* __restrict__ projb,
                       const float* __restrict__ mu,
                       const float* __restrict__ isg,
                       int nE, int nL)
{
    const int idx = blockIdx.x * 256 + threadIdx.x;
    if (idx >= nE * nL) return;
    const int i = idx / nE;
    const int e = idx - i * nE;

    const float W00 = __ldg(&projW[i*4+0]), W01 = __ldg(&projW[i*4+1]);
    const float W10 = __ldg(&projW[i*4+2]), W11 = __ldg(&projW[i*4+3]);
    const float b0 = __ldg(&projb[i*2+0]), b1 = __ldg(&projb[i*2+1]);

    const float2 ps = __ldg(&((const float2*)pseudo)[e]);
    const float u0 = tanhf(fmaf(ps.y, W10, fmaf(ps.x, W00, b0)));
    const float u1 = tanhf(fmaf(ps.y, W11, fmaf(ps.x, W01, b1)));

    float4 v;
    {
        float q0 = __ldg(&isg[i*6+0]), q1 = __ldg(&isg[i*6+1]);
        float d0 = u0 - __ldg(&mu[i*6+0]), d1 = u1 - __ldg(&mu[i*6+1]);
        v.x = __expf(-0.5f * (d0*d0*q0*q0 + d1*d1*q1*q1));
        q0 = __ldg(&isg[i*6+2]); q1 = __ldg(&isg[i*6+3]);
        d0 = u0 - __ldg(&mu[i*6+2]); d1 = u1 - __ldg(&mu[i*6+3]);
        v.y = __expf(-0.5f * (d0*d0*q0*q0 + d1*d1*q1*q1));
        q0 = __ldg(&isg[i*6+4]); q1 = __ldg(&isg[i*6+5]);
        d0 = u0 - __ldg(&mu[i*6+4]); d1 = u1 - __ldg(&mu[i*6+5]);
        v.z = __expf(-0.5f * (d0*d0*q0*q0 + d1*d1*q1*q1));
    }
    v.w = __int_as_float(__ldg(&colind[e]));
    wpack_buf[(size_t)i * nE + e] = v;
}

// ---------------------------------------------------------------------------
// Prep 2: rearrange fcW into WP layout (K-pair-packed, warp-coalesced).
// ---------------------------------------------------------------------------
__global__ void prep_kernel(const float* __restrict__ fcW, int nL)
{
    const int idx = blockIdx.x * 256 + threadIdx.x;
    const int total = nL * 96 * 32;
    if (idx >= total) return;
    const int i  = idx / (96 * 32);
    const int rem = idx - i * 96 * 32;
    const int pp = rem >> 5, t = rem & 31;
    const float* W = fcW + i * 64 * 192;
    const int p0 = 2 * pp, p1 = 2 * pp + 1;
    const int k0 = p0 >> 6, j0 = p0 & 63;
    const int k1 = p1 >> 6, j1 = p1 & 63;
    float4 v;
    v.x = W[j0 * 192 + k0 * 64 + 2 * t];
    v.y = W[j1 * 192 + k1 * 64 + 2 * t];
    v.z = W[j0 * 192 + k0 * 64 + 2 * t + 1];
    v.w = W[j1 * 192 + k1 * 64 + 2 * t + 1];
    ((float4*)WP_buf)[idx] = v;
}

// ---------------------------------------------------------------------------
// Fused layer kernel.
//   Phase A: half-warp node pairing — lanes 0-15 gather node A (16B/lane),
//            lanes 16-31 node B. One LDG.128 = both rows (512B/instr).
//   Phase B: block GEMM (round-8 proven): g LDS.128 broadcast + W LDG (L1).
// ---------------------------------------------------------------------------
__global__ __launch_bounds__(256, 3)
void fused_layer(const float* __restrict__ h,
                 const int*   __restrict__ rowptr,
                 const float4* __restrict__ wpack,   // [E] this layer
                 const float* __restrict__ WP,       // [96][32] float4
                 float* __restrict__ out, int n)
{
    extern __shared__ float smem[];
    float* gs = smem;                               // [64][192]
    float4* wf4 = (float4*)(smem + GS_FLOATS);      // [8 warps][STG_F4]

    const int tid = threadIdx.x;
    const int wid = tid >> 5;
    const int lid = tid & 31;

    const ulonglong2* __restrict__ wpv = (const ulonglong2*)WP;

    // phase-A lane mapping
    const int half = lid >> 4;        // 0 = node A, 1 = node B
    const int fl   = lid & 15;        // feature group 4fl..4fl+3

    // phase-B mapping
    const int tx = tid & 31;          // cols 2tx, 2tx+1
    const int ty = tid >> 5;          // rows 8ty..+7

    const int ntiles = (n + TILE - 1) / TILE;
    for (int tile = blockIdx.x; tile < ntiles; tile += gridDim.x) {
        const int r0 = tile * TILE;
        const int rows = min(TILE, n - r0);
        __syncthreads();   // prev phase-B readers done

        // ---------------- Phase A: paired gather -------------------------
        {
            float4* stA = wf4 + wid * STG_F4;
            float4* stB = stA + 33;          // 16B pad -> distinct banks

            for (int jp = 0; jp < 4; jp++) {
                const int rA = (wid << 3) + (jp << 1);
                const int nodeA = r0 + rA;
                if (nodeA >= n) break;
                const int nodeB = nodeA + 1;
                const bool hasB = (nodeB < n);

                const int e0A = rowptr[nodeA];
                const int cA  = rowptr[nodeA + 1] - e0A;
                const int e0B = hasB ? rowptr[nodeB] : 0;
                const int cB  = hasB ? rowptr[nodeB + 1] - e0B : -1;

                if (cA == 32 && cB == 32) {
                    // fast path: fixed-degree pair
                    stA[lid] = __ldg(&wpack[e0A + lid]);
                    stB[lid] = __ldg(&wpack[e0B + lid]);
                    __syncwarp();

                    const float4* stg = half ? stB : stA;
                    const float* hb = h + 4 * fl;
                    ull a0l = 0ULL, a0h = 0ULL, a1l = 0ULL, a1h = 0ULL,
                        a2l = 0ULL, a2h = 0ULL;

                    #pragma unroll 8
                    for (int t = 0; t < 32; t++) {
                        const float4 wt = stg[t];
                        const int src = __float_as_int(wt.w);
                        const ulonglong2 hv =
                            *(const ulonglong2*)(hb + (size_t)src * FDIM);
                        ull w0d, w1d, w2d;
                        PACK_DUP(w0d, wt.x); PACK_DUP(w1d, wt.y); PACK_DUP(w2d, wt.z);
                        FMA_F32X2(a0l, hv.x, w0d, a0l);
                        FMA_F32X2(a0h, hv.y, w0d, a0h);
                        FMA_F32X2(a1l, hv.x, w1d, a1l);
                        FMA_F32X2(a1h, hv.y, w1d, a1h);
                        FMA_F32X2(a2l, hv.x, w2d, a2l);
                        FMA_F32X2(a2h, hv.y, w2d, a2h);
                    }
                    __syncwarp();

                    float* grow = gs + (rA + half) * KF + 4 * fl;
                    ulonglong2 v;
                    v.x = a0l; v.y = a0h; *(ulonglong2*)(grow      ) = v;
                    v.x = a1l; v.y = a1h; *(ulonglong2*)(grow +  64) = v;
                    v.x = a2l; v.y = a2h; *(ulonglong2*)(grow + 128) = v;
                } else {
                    // general fallback: per node, float2 lanes (proven body)
                    for (int s = 0; s < 2; s++) {
                        const int node = nodeA + s;
                        if (node >= n) break;
                        const int e0 = rowptr[node], e1 = rowptr[node + 1];
                        ull A0 = 0ULL, A1 = 0ULL, A2 = 0ULL;
                        for (int base = e0; base < e1; base += 32) {
                            const int cnt = min(32, e1 - base);
                            if (lid < cnt)
                                stA[lid] = __ldg(&wpack[base + lid]);
                            __syncwarp();
                            for (int t = 0; t < cnt; t++) {
                                const float4 wt = stA[t];
                                const int src = __float_as_int(wt.w);
                                const ull hv = *(const ull*)(h + (size_t)src * FDIM + 2 * lid);
                                ull w0d, w1d, w2d;
                                PACK_DUP(w0d, wt.x); PACK_DUP(w1d, wt.y); PACK_DUP(w2d, wt.z);
                                FMA_F32X2(A0, hv, w0d, A0);
                                FMA_F32X2(A1, hv, w1d, A1);
                                FMA_F32X2(A2, hv, w2d, A2);
                            }
                            __syncwarp();
                        }
                        *(ull*)(gs + (rA + s) * KF + 2 * lid      ) = A0;
                        *(ull*)(gs + (rA + s) * KF + 2 * lid +  64) = A1;
                        *(ull*)(gs + (rA + s) * KF + 2 * lid + 128) = A2;
                    }
                }
            }
        }
        __syncthreads();

        // ---------------- Phase B: GEMM ----------------------------------
        {
            const ull* gp = (const ull*)(gs + (ty << 3) * KF);

            ull acc[8][2];
            #pragma unroll
            for (int i = 0; i < 8; i++) { acc[i][0] = 0ULL; acc[i][1] = 0ULL; }

            #pragma unroll 2
            for (int pp2 = 0; pp2 < 48; pp2++) {
                const ulonglong2 wA = __ldg(&wpv[(2 * pp2    ) * 32 + tx]);
                const ulonglong2 wB = __ldg(&wpv[(2 * pp2 + 1) * 32 + tx]);
                #pragma unroll
                for (int i = 0; i < 8; i++) {
                    const ulonglong2 gv = *(const ulonglong2*)(gp + i * 96 + 2 * pp2);
                    FMA_F32X2(acc[i][0], gv.x, wA.x, acc[i][0]);
                    FMA_F32X2(acc[i][1], gv.x, wA.y, acc[i][1]);
                    FMA_F32X2(acc[i][0], gv.y, wB.x, acc[i][0]);
                    FMA_F32X2(acc[i][1], gv.y, wB.y, acc[i][1]);
                }
            }

            #pragma unroll
            for (int i = 0; i < 8; i++) {
                const int r = (ty << 3) + i;
                if (r < rows) {
                    float e0, o0, e1, o1;
                    UNPACK2(e0, o0, acc[i][0]);
                    UNPACK2(e1, o1, acc[i][1]);
                    *(float2*)&out[(size_t)(r0 + r) * FDIM + 2 * tx] =
                        make_float2(e0 + o0, e1 + o1);
                }
            }
        }
    }
}

// ---------------------------------------------------------------------------
extern "C" void kernel_launch(void* const* d_in, const int* in_sizes, int n_in,
                              void* d_out, int out_size)
{
    const float* feat   = (const float*)d_in[0];
    const float* pseudo = (const float*)d_in[1];
    const int*   rowptr = (const int*)  d_in[2];
    const int*   colind = (const int*)  d_in[3];
    const float* projW  = (const float*)d_in[4];
    const float* projb  = (const float*)d_in[5];
    const float* fcW    = (const float*)d_in[6];
    const float* mu     = (const float*)d_in[7];
    const float* isg    = (const float*)d_in[8];

    const int n  = in_sizes[0] / FDIM;
    const int nE = in_sizes[3];
    const int nL = in_sizes[6] / (FDIM * KF);

    void *hap, *hbp, *wpp, *wkp;
    cudaGetSymbolAddress(&hap, h_bufA);
    cudaGetSymbolAddress(&hbp, h_bufB);
    cudaGetSymbolAddress(&wpp, WP_buf);
    cudaGetSymbolAddress(&wkp, wpack_buf);
    float* hbufs[2] = { (float*)hap, (float*)hbp };
    const float* WP = (const float*)wpp;
    const float4* wpack = (const float4*)wkp;

    cudaFuncSetAttribute(fused_layer, cudaFuncAttributeMaxDynamicSharedMemorySize, SMEM_BYTES);

    prep_kernel<<<(nL * 96 * 32 + 255) / 256, 256>>>(fcW, nL);
    prep_w<<<((size_t)nE * nL + 255) / 256, 256>>>(pseudo, colind, projW, projb,
                                                   mu, isg, nE, nL);

    const int ntiles = (n + TILE - 1) / TILE;
    const int maxg = 3 * 148;
    const int grid = ntiles < maxg ? ntiles : maxg;

    const float* hin = feat;
    for (int i = 0; i < nL; i++) {
        float* hout = (i == nL - 1) ? (float*)d_out : hbufs[i & 1];
        fused_layer<<<grid, 256, SMEM_BYTES>>>(hin, rowptr,
                                               wpack + (size_t)i * nE,
                                               WP + (size_t)i * 96 * 32 * 4,
                                               hout, n);
        hin = hout;
    }
}

// round 14
// speedup vs baseline: 1.3030x; 1.0181x over previous
#include <cuda_runtime.h>
#include <cuda_bf16.h>
#include <cstddef>
#include <cstdint>

// Problem constants: N=50000, DEG=32, E=N*32, F=64, K=3, DIM=2, L=3
#define MAXN 50000
#define MAXE (MAXN * 32)
#define FDIM 64
#define KF   192        // K * F
#define TILE 64

// smem: gs[64][192] only (staging lives inside the rows being gathered)
#define GS_FLOATS (TILE * KF)
#define SMEM_BYTES  (GS_FLOATS * 4 + 1024)   // 50176 B -> 3+ CTAs/SM

__device__ float h_bufA[(size_t)MAXN * FDIM];
__device__ float h_bufB[(size_t)MAXN * FDIM];
// WP[layer][pp][t] float4 = {Wk[2pp][2t], Wk[2pp+1][2t], Wk[2pp][2t+1], Wk[2pp+1][2t+1]}
__device__ float WP_buf[3 * 96 * 32 * 4];
// wpack[layer][e] = {w0, w1, w2, bitcast(src)}
__device__ float4 wpack_buf[(size_t)3 * MAXE];

// Packed fp32x2 FMA (sm_103a FFMA2 — only reachable via PTX)
#define FMA_F32X2(d, a, b, c) \
    asm("fma.rn.f32x2 %0, %1, %2, %3;" : "=l"(d) : "l"(a), "l"(b), "l"(c))
#define PACK_DUP(d, x) \
    asm("mov.b64 %0, {%1, %1};" : "=l"(d) : "f"(x))
#define UNPACK2(lo, hi, v) \
    asm("mov.b64 {%0, %1}, %2;" : "=f"(lo), "=f"(hi) : "l"(v))

typedef unsigned long long ull;

// ---------------------------------------------------------------------------
// Prep 1: per-edge Gaussian weights for every layer.
// ---------------------------------------------------------------------------
__global__ void prep_w(const float* __restrict__ pseudo,
                       const int*   __restrict__ colind,
                       const float* __restrict__ projW,
                       const float* __restrict__ projb,
                       const float* __restrict__ mu,
                       const float* __restrict__ isg,
                       int nE, int nL)
{
    const int idx = blockIdx.x * 256 + threadIdx.x;
    if (idx >= nE * nL) return;
    const int i = idx / nE;
    const int e = idx - i * nE;

    const float W00 = __ldg(&projW[i*4+0]), W01 = __ldg(&projW[i*4+1]);
    const float W10 = __ldg(&projW[i*4+2]), W11 = __ldg(&projW[i*4+3]);
    const float b0 = __ldg(&projb[i*2+0]), b1 = __ldg(&projb[i*2+1]);

    const float2 ps = __ldg(&((const float2*)pseudo)[e]);
    const float u0 = tanhf(fmaf(ps.y, W10, fmaf(ps.x, W00, b0)));
    const float u1 = tanhf(fmaf(ps.y, W11, fmaf(ps.x, W01, b1)));

    float4 v;
    {
        float q0 = __ldg(&isg[i*6+0]), q1 = __ldg(&isg[i*6+1]);
        float d0 = u0 - __ldg(&mu[i*6+0]), d1 = u1 - __ldg(&mu[i*6+1]);
        v.x = __expf(-0.5f * (d0*d0*q0*q0 + d1*d1*q1*q1));
        q0 = __ldg(&isg[i*6+2]); q1 = __ldg(&isg[i*6+3]);
        d0 = u0 - __ldg(&mu[i*6+2]); d1 = u1 - __ldg(&mu[i*6+3]);
        v.y = __expf(-0.5f * (d0*d0*q0*q0 + d1*d1*q1*q1));
        q0 = __ldg(&isg[i*6+4]); q1 = __ldg(&isg[i*6+5]);
        d0 = u0 - __ldg(&mu[i*6+4]); d1 = u1 - __ldg(&mu[i*6+5]);
        v.z = __expf(-0.5f * (d0*d0*q0*q0 + d1*d1*q1*q1));
    }
    v.w = __int_as_float(__ldg(&colind[e]));
    wpack_buf[(size_t)i * nE + e] = v;
}

// ---------------------------------------------------------------------------
// Prep 2: rearrange fcW into WP layout (K-pair-packed, warp-coalesced).
// ---------------------------------------------------------------------------
__global__ void prep_kernel(const float* __restrict__ fcW, int nL)
{
    const int idx = blockIdx.x * 256 + threadIdx.x;
    const int total = nL * 96 * 32;
    if (idx >= total) return;
    const int i  = idx / (96 * 32);
    const int rem = idx - i * 96 * 32;
    const int pp = rem >> 5, t = rem & 31;
    const float* W = fcW + i * 64 * 192;
    const int p0 = 2 * pp, p1 = 2 * pp + 1;
    const int k0 = p0 >> 6, j0 = p0 & 63;
    const int k1 = p1 >> 6, j1 = p1 & 63;
    float4 v;
    v.x = W[j0 * 192 + k0 * 64 + 2 * t];
    v.y = W[j1 * 192 + k1 * 64 + 2 * t];
    v.z = W[j0 * 192 + k0 * 64 + 2 * t + 1];
    v.w = W[j1 * 192 + k1 * 64 + 2 * t + 1];
    ((float4*)WP_buf)[idx] = v;
}

// ---------------------------------------------------------------------------
// Fused layer kernel.
//   Phase A: stage ALL 8 nodes' wpack into the warp's 8 gs rows up front
//            (8 independent LDG.128 bursts, one wait), then 4 pair-gathers
//            back-to-back (half-warp pairing: lanes 0-15 node A, 16-31 B).
//   Phase B: block GEMM (proven): g LDS.128 broadcast + W coalesced LDG (L1).
// ---------------------------------------------------------------------------
__global__ __launch_bounds__(256, 3)
void fused_layer(const float* __restrict__ h,
                 const int*   __restrict__ rowptr,
                 const float4* __restrict__ wpack,   // [E] this layer
                 const float* __restrict__ WP,       // [96][32] float4
                 float* __restrict__ out, int n)
{
    extern __shared__ float smem[];
    float* gs = smem;                               // [64][192]

    const int tid = threadIdx.x;
    const int wid = tid >> 5;
    const int lid = tid & 31;

    const ulonglong2* __restrict__ wpv = (const ulonglong2*)WP;

    // phase-A lane mapping
    const int half = lid >> 4;        // 0 = node A, 1 = node B
    const int fl   = lid & 15;        // feature group 4fl..4fl+3

    // phase-B mapping
    const int tx = tid & 31;          // cols 2tx, 2tx+1
    const int ty = tid >> 5;          // rows 8ty..+7

    const int rbase = wid << 3;

    const int ntiles = (n + TILE - 1) / TILE;
    for (int tile = blockIdx.x; tile < ntiles; tile += gridDim.x) {
        const int r0 = tile * TILE;
        const int rows = min(TILE, n - r0);
        __syncthreads();   // prev phase-B readers done

        // ---------------- Phase A ---------------------------------------
        {
            // check fast path: warp's 8 nodes all present, all degree-32
            bool fast = (r0 + rbase + 8 <= n);
            int e0s[8];
            if (fast) {
                #pragma unroll
                for (int s = 0; s < 8; s++) {
                    const int nd = r0 + rbase + s;
                    const int a = __ldg(&rowptr[nd]);
                    const int b = __ldg(&rowptr[nd + 1]);
                    e0s[s] = a;
                    fast = fast && (b - a == 32);
                }
            }

            if (fast) {
                // stage all 8 nodes' wpack into their own gs rows (512B each)
                #pragma unroll
                for (int s = 0; s < 8; s++)
                    ((float4*)(gs + (rbase + s) * KF))[lid] =
                        __ldg(&wpack[e0s[s] + lid]);
                __syncwarp();

                #pragma unroll
                for (int jp = 0; jp < 4; jp++) {
                    const int rA = rbase + (jp << 1);
                    const float4* stg = (const float4*)(gs + (rA + half) * KF);
                    const float* hb = h + 4 * fl;
                    ull a0l = 0ULL, a0h = 0ULL, a1l = 0ULL, a1h = 0ULL,
                        a2l = 0ULL, a2h = 0ULL;

                    #pragma unroll 8
                    for (int t = 0; t < 32; t++) {
                        const float4 wt = stg[t];
                        const int src = __float_as_int(wt.w);
                        const ulonglong2 hv =
                            *(const ulonglong2*)(hb + (size_t)src * FDIM);
                        ull w0d, w1d, w2d;
                        PACK_DUP(w0d, wt.x); PACK_DUP(w1d, wt.y); PACK_DUP(w2d, wt.z);
                        FMA_F32X2(a0l, hv.x, w0d, a0l);
                        FMA_F32X2(a0h, hv.y, w0d, a0h);
                        FMA_F32X2(a1l, hv.x, w1d, a1l);
                        FMA_F32X2(a1h, hv.y, w1d, a1h);
                        FMA_F32X2(a2l, hv.x, w2d, a2l);
                        FMA_F32X2(a2h, hv.y, w2d, a2h);
                    }
                    __syncwarp();   // all lanes done reading rows rA, rA+1

                    float* grow = gs + (rA + half) * KF + 4 * fl;
                    ulonglong2 v;
                    v.x = a0l; v.y = a0h; *(ulonglong2*)(grow      ) = v;
                    v.x = a1l; v.y = a1h; *(ulonglong2*)(grow +  64) = v;
                    v.x = a2l; v.y = a2h; *(ulonglong2*)(grow + 128) = v;
                }
            } else {
                // general fallback: per node, float2 lanes, stage in own row
                for (int s = 0; s < 8; s++) {
                    const int node = r0 + rbase + s;
                    if (node >= n) break;
                    float4* stage = (float4*)(gs + (rbase + s) * KF);
                    const int e0 = __ldg(&rowptr[node]);
                    const int e1 = __ldg(&rowptr[node + 1]);
                    ull A0 = 0ULL, A1 = 0ULL, A2 = 0ULL;
                    for (int base = e0; base < e1; base += 32) {
                        const int cnt = min(32, e1 - base);
                        if (lid < cnt)
                            stage[lid] = __ldg(&wpack[base + lid]);
                        __syncwarp();
                        for (int t = 0; t < cnt; t++) {
                            const float4 wt = stage[t];
                            const int src = __float_as_int(wt.w);
                            const ull hv = *(const ull*)(h + (size_t)src * FDIM + 2 * lid);
                            ull w0d, w1d, w2d;
                            PACK_DUP(w0d, wt.x); PACK_DUP(w1d, wt.y); PACK_DUP(w2d, wt.z);
                            FMA_F32X2(A0, hv, w0d, A0);
                            FMA_F32X2(A1, hv, w1d, A1);
                            FMA_F32X2(A2, hv, w2d, A2);
                        }
                        __syncwarp();
                    }
                    *(ull*)(gs + (rbase + s) * KF + 2 * lid      ) = A0;
                    *(ull*)(gs + (rbase + s) * KF + 2 * lid +  64) = A1;
                    *(ull*)(gs + (rbase + s) * KF + 2 * lid + 128) = A2;
                    __syncwarp();
                }
            }
        }
        __syncthreads();

        // ---------------- Phase B: GEMM ----------------------------------
        {
            const ull* gp = (const ull*)(gs + (ty << 3) * KF);

            ull acc[8][2];
            #pragma unroll
            for (int i = 0; i < 8; i++) { acc[i][0] = 0ULL; acc[i][1] = 0ULL; }

            #pragma unroll 2
            for (int pp2 = 0; pp2 < 48; pp2++) {
                const ulonglong2 wA = __ldg(&wpv[(2 * pp2    ) * 32 + tx]);
                const ulonglong2 wB = __ldg(&wpv[(2 * pp2 + 1) * 32 + tx]);
                #pragma unroll
                for (int i = 0; i < 8; i++) {
                    const ulonglong2 gv = *(const ulonglong2*)(gp + i * 96 + 2 * pp2);
                    FMA_F32X2(acc[i][0], gv.x, wA.x, acc[i][0]);
                    FMA_F32X2(acc[i][1], gv.x, wA.y, acc[i][1]);
                    FMA_F32X2(acc[i][0], gv.y, wB.x, acc[i][0]);
                    FMA_F32X2(acc[i][1], gv.y, wB.y, acc[i][1]);
                }
            }

            #pragma unroll
            for (int i = 0; i < 8; i++) {
                const int r = (ty << 3) + i;
                if (r < rows) {
                    float e0, o0, e1, o1;
                    UNPACK2(e0, o0, acc[i][0]);
                    UNPACK2(e1, o1, acc[i][1]);
                    *(float2*)&out[(size_t)(r0 + r) * FDIM + 2 * tx] =
                        make_float2(e0 + o0, e1 + o1);
                }
            }
        }
    }
}

// ---------------------------------------------------------------------------
extern "C" void kernel_launch(void* const* d_in, const int* in_sizes, int n_in,
                              void* d_out, int out_size)
{
    const float* feat   = (const float*)d_in[0];
    const float* pseudo = (const float*)d_in[1];
    const int*   rowptr = (const int*)  d_in[2];
    const int*   colind = (const int*)  d_in[3];
    const float* projW  = (const float*)d_in[4];
    const float* projb  = (const float*)d_in[5];
    const float* fcW    = (const float*)d_in[6];
    const float* mu     = (const float*)d_in[7];
    const float* isg    = (const float*)d_in[8];

    const int n  = in_sizes[0] / FDIM;
    const int nE = in_sizes[3];
    const int nL = in_sizes[6] / (FDIM * KF);

    void *hap, *hbp, *wpp, *wkp;
    cudaGetSymbolAddress(&hap, h_bufA);
    cudaGetSymbolAddress(&hbp, h_bufB);
    cudaGetSymbolAddress(&wpp, WP_buf);
    cudaGetSymbolAddress(&wkp, wpack_buf);
    float* hbufs[2] = { (float*)hap, (float*)hbp };
    const float* WP = (const float*)wpp;
    const float4* wpack = (const float4*)wkp;

    cudaFuncSetAttribute(fused_layer, cudaFuncAttributeMaxDynamicSharedMemorySize, SMEM_BYTES);

    prep_kernel<<<(nL * 96 * 32 + 255) / 256, 256>>>(fcW, nL);
    prep_w<<<((size_t)nE * nL + 255) / 256, 256>>>(pseudo, colind, projW, projb,
                                                   mu, isg, nE, nL);

    const int ntiles = (n + TILE - 1) / TILE;
    const int maxg = 3 * 148;
    const int grid = ntiles < maxg ? ntiles : maxg;

    const float* hin = feat;
    for (int i = 0; i < nL; i++) {
        float* hout = (i == nL - 1) ? (float*)d_out : hbufs[i & 1];
        fused_layer<<<grid, 256, SMEM_BYTES>>>(hin, rowptr,
                                               wpack + (size_t)i * nE,
                                               WP + (size_t)i * 96 * 32 * 4,
                                               hout, n);
        hin = hout;
    }
}